// round 17
// baseline (speedup 1.0000x reference)
#include <cuda_runtime.h>
#include <math.h>

#define NP     4096
#define TOTAL  65536
#define ROWS   32
#define NBX    64
#define NBY    64
#define NCELL  (NBX * NBY)          // 4096
#define LOV    (-5.0f)
#define HIV    (5.0f)
#define WX     ((HIV - LOV) / NBX)  // 0.15625
#define WY     ((HIV - LOV) / NBY)
#define INVX   ((float)NBX / (HIV - LOV))
#define INVY   ((float)NBY / (HIV - LOV))
#define PADX   1
#define PADY   1
#define BT     128
#define QPB    128
#define NBLK   (2 * TOTAL / QPB)    // 1024
#define FULLM  0xFFFFFFFFu

__device__ float4 g_sorted[2 * TOTAL];
__device__ int    g_hist8[ROWS][8][NCELL];
__device__ int    g_segstart[ROWS][8][NCELL];
__device__ int    g_cellstart[ROWS][NCELL + 1];
__device__ float  g_partial[NBLK];
__device__ unsigned g_done;

__device__ __forceinline__ int binx(float v) {
    int b = (int)((v - LOV) * INVX);
    return min(max(b, 0), NBX - 1);
}
__device__ __forceinline__ int biny(float v) {
    int b = (int)((v - LOV) * INVY);
    return min(max(b, 0), NBY - 1);
}
// Serpentine cell id: odd x-bins store y reversed (keeps consecutive-sorted
// queries y-local across x-bin boundaries).
__device__ __forceinline__ int cellof(float vx, float vy) {
    int xb = binx(vx), yb = biny(vy);
    int yy = (xb & 1) ? (NBY - 1 - yb) : yb;
    return (xb << 6) | yy;
}

__global__ __launch_bounds__(256) void hist_kernel(const float* __restrict__ x,
                                                   const float* __restrict__ y) {
    int row = blockIdx.x >> 3, seg = blockIdx.x & 7;
    const float* src = ((row >= 16) ? y : x) + (size_t)(row & 15) * NP * 3;
    __shared__ int h[NCELL];
    int tid = threadIdx.x;
    #pragma unroll
    for (int i = 0; i < NCELL / 256; i++) h[tid + 256 * i] = 0;
    __syncthreads();
    int p0 = seg * 512 + tid * 2;
    const float2* s2 = (const float2*)(src + 3 * p0);
    float2 ab = s2[0], ca = s2[1], bc = s2[2];
    atomicAdd(&h[cellof(ab.x, ab.y)], 1);
    atomicAdd(&h[cellof(ca.y, bc.x)], 1);
    __syncthreads();
    #pragma unroll
    for (int i = 0; i < NCELL / 256; i++)
        g_hist8[row][seg][tid + 256 * i] = h[tid + 256 * i];
}

// Per-row: sum 8 segs -> scan 4096 cells -> cellstart + per-seg starts.
__global__ __launch_bounds__(512) void prefix_kernel() {
    int row = blockIdx.x, tid = threadIdx.x;
    if (row == 0 && tid == 0) g_done = 0;
    __shared__ int wsum[16];
    int lane = tid & 31, wno = tid >> 5;
    int c0 = tid * 8;

    int v[8];
    int tsum = 0;
    #pragma unroll
    for (int i = 0; i < 8; i++) {
        int s = 0;
        #pragma unroll
        for (int k = 0; k < 8; k++) s += g_hist8[row][k][c0 + i];
        v[i] = s;
        tsum += s;
    }
    // warp inclusive scan of thread sums
    int incl = tsum;
    #pragma unroll
    for (int o = 1; o < 32; o <<= 1) {
        int t = __shfl_up_sync(FULLM, incl, o);
        if (lane >= o) incl += t;
    }
    if (lane == 31) wsum[wno] = incl;
    __syncthreads();
    if (tid == 0) {
        int run = 0;
        #pragma unroll
        for (int w = 0; w < 16; w++) { int t = wsum[w]; wsum[w] = run; run += t; }
    }
    __syncthreads();
    int thrExcl = wsum[wno] + (incl - tsum);

    int run = thrExcl;
    #pragma unroll
    for (int i = 0; i < 8; i++) {
        int c = c0 + i;
        g_cellstart[row][c] = run;
        int r2 = run;
        #pragma unroll
        for (int k = 0; k < 8; k++) {
            g_segstart[row][k][c] = r2;
            r2 += g_hist8[row][k][c];
        }
        run = r2;
    }
    if (tid == 511) g_cellstart[row][NCELL] = run;   // == NP
}

__global__ __launch_bounds__(256) void scatter_kernel(const float* __restrict__ x,
                                                      const float* __restrict__ y) {
    int row = blockIdx.x >> 3, seg = blockIdx.x & 7;
    const float* src = ((row >= 16) ? y : x) + (size_t)(row & 15) * NP * 3;
    __shared__ int cnt[NCELL];
    int tid = threadIdx.x;
    #pragma unroll
    for (int i = 0; i < NCELL / 256; i++) cnt[tid + 256 * i] = 0;
    __syncthreads();
    int p0 = seg * 512 + tid * 2;
    const float2* s2 = (const float2*)(src + 3 * p0);
    float2 ab = s2[0], ca = s2[1], bc = s2[2];
    float4* dst = g_sorted + (size_t)row * NP;
    {
        int c = cellof(ab.x, ab.y);
        int pos = g_segstart[row][seg][c] + atomicAdd(&cnt[c], 1);
        dst[pos] = make_float4(ab.x, ab.y, ca.x,
                               0.5f * (ab.x * ab.x + ab.y * ab.y + ca.x * ca.x));
    }
    {
        int c = cellof(ca.y, bc.x);
        int pos = g_segstart[row][seg][c] + atomicAdd(&cnt[c], 1);
        dst[pos] = make_float4(ca.y, bc.x, bc.y,
                               0.5f * (ca.y * ca.y + bc.x * bc.x + bc.y * bc.y));
    }
}

__global__ __launch_bounds__(BT) void chamfer_kernel(float* __restrict__ out) {
    __shared__ float4 qbuf[QPB];
    __shared__ float  sdist[QPB];
    __shared__ int    slist[QPB];
    __shared__ float  smin[QPB];
    __shared__ int    scount;
    __shared__ int    sIsLast;

    int blk = blockIdx.x;                 // 1024 blocks
    int dir = blk >> 9;
    int b   = (blk >> 5) & 15;
    int qt  = blk & 31;
    int tid = threadIdx.x;
    int lane = tid & 31;
    int wid  = tid >> 5;

    int qRow  = dir ? (16 + b) : b;
    int dbRow = dir ? b : (16 + b);
    const float4* db = g_sorted + (size_t)dbRow * NP;
    const int*    cs = g_cellstart[dbRow];

    if (tid == 0) scount = 0;
    float4 q = g_sorted[(size_t)qRow * NP + qt * QPB + tid];
    qbuf[tid] = q;
    __syncthreads();

    // Warp-uniform 2D window: x-bin span + PADX, y-bin span + PADY.
    int xb = binx(q.x), yb = biny(q.y);
    int kLx = max((int)__reduce_min_sync(FULLM, (unsigned)xb) - PADX, 0);
    int kRx = min((int)__reduce_max_sync(FULLM, (unsigned)xb) + PADX, NBX - 1);
    int yL  = max((int)__reduce_min_sync(FULLM, (unsigned)yb) - PADY, 0);
    int yR  = min((int)__reduce_max_sync(FULLM, (unsigned)yb) + PADY, NBY - 1);

    // Scan the rect: per x-bin one contiguous y segment (serpentine-aware).
    float m0 = 1e30f, m1 = 1e30f, m2 = 1e30f, m3 = 1e30f;
    for (int x2 = kLx; x2 <= kRx; ++x2) {
        int base = x2 << 6;
        int c0 = (x2 & 1) ? (base + NBY - 1 - yR) : (base + yL);
        int c1 = (x2 & 1) ? (base + NBY - yL)     : (base + yR + 1);
        int lo = __ldg(cs + c0);
        int hi = __ldg(cs + c1);
        int j = lo;
        for (; j + 4 <= hi; j += 4) {
            float4 p0 = __ldg(&db[j]);
            float4 p1 = __ldg(&db[j + 1]);
            float4 p2 = __ldg(&db[j + 2]);
            float4 p3 = __ldg(&db[j + 3]);
            m0 = fminf(m0, fmaf(-q.x, p0.x, fmaf(-q.y, p0.y, fmaf(-q.z, p0.z, p0.w))));
            m1 = fminf(m1, fmaf(-q.x, p1.x, fmaf(-q.y, p1.y, fmaf(-q.z, p1.z, p1.w))));
            m2 = fminf(m2, fmaf(-q.x, p2.x, fmaf(-q.y, p2.y, fmaf(-q.z, p2.z, p2.w))));
            m3 = fminf(m3, fmaf(-q.x, p3.x, fmaf(-q.y, p3.y, fmaf(-q.z, p3.z, p3.w))));
        }
        for (; j < hi; ++j) {
            float4 p = __ldg(&db[j]);
            m0 = fminf(m0, fmaf(-q.x, p.x, fmaf(-q.y, p.y, fmaf(-q.z, p.z, p.w))));
        }
    }
    float m = fminf(fminf(m0, m1), fminf(m2, m3));

    // Exact per-lane bound: every unscanned point violates >=1 rect side, so
    // done iff each side is a domain boundary or its gap^2 covers the best.
    float thr = q.w + m;                        // 0.5 * d_best^2 upper bound
    float gxL = q.x - (LOV + (float)kLx * WX);
    float gxR = (LOV + (float)(kRx + 1) * WX) - q.x;
    float gyL = q.y - (LOV + (float)yL * WY);
    float gyR = (LOV + (float)(yR + 1) * WY) - q.y;
    bool done = ((kLx == 0)       || (0.5f * gxL * gxL >= thr))
             && ((kRx == NBX - 1) || (0.5f * gxR * gxR >= thr))
             && ((yL == 0)        || (0.5f * gyL * gyL >= thr))
             && ((yR == NBY - 1)  || (0.5f * gyR * gyR >= thr));

    sdist[tid] = sqrtf(1e-6f + fmaxf(2.0f * thr, 0.0f));

    unsigned mk = __ballot_sync(FULLM, !done);
    int nneed = __popc(mk);
    if (nneed) {
        int base = 0;
        if (lane == 0) base = atomicAdd(&scount, nneed);
        base = __shfl_sync(FULLM, base, 0);
        if (!done) {
            int rank = __popc(mk & ((1u << lane) - 1));
            slist[base + rank] = tid;
            smin[base + rank] = m;
        }
    }
    __syncthreads();

    // Block-local exact phase 2: one warp per spilled query, 1D x-range scan
    // (contiguous in memory: x-bin-major layout), m as upper bound.
    int ns = scount;
    for (int i = wid; i < ns; i += BT / 32) {
        int t = slist[i];
        float mm = smin[i];
        float4 q2 = qbuf[t];
        float d1 = sqrtf(fmaxf(2.0f * (q2.w + mm), 0.0f)) * 1.0005f + 1e-5f;
        int lo2 = __ldg(cs + (binx(q2.x - d1) << 6));
        int hi2 = __ldg(cs + ((binx(q2.x + d1) + 1) << 6));
        for (int jj = lo2 + lane; jj < hi2; jj += 32) {
            float4 p = __ldg(&db[jj]);
            mm = fminf(mm, fmaf(-q2.x, p.x, fmaf(-q2.y, p.y, fmaf(-q2.z, p.z, p.w))));
        }
        #pragma unroll
        for (int o = 16; o; o >>= 1)
            mm = fminf(mm, __shfl_xor_sync(FULLM, mm, o));
        if (lane == 0)
            sdist[t] = sqrtf(1e-6f + fmaxf(2.0f * (q2.w + mm), 0.0f));
    }
    __syncthreads();

    // Deterministic fixed-tree reduction over the block's 128 distances.
    #pragma unroll
    for (int st = BT / 2; st > 0; st >>= 1) {
        if (tid < st) sdist[tid] += sdist[tid + st];
        __syncthreads();
    }
    if (tid == 0) g_partial[blk] = sdist[0];

    // Fused finalize: last block sums all partials (fixed order).
    __threadfence();
    if (tid == 0) {
        unsigned t = atomicAdd(&g_done, 1u);
        sIsLast = (t == NBLK - 1);
    }
    __syncthreads();
    if (sIsLast) {
        float v = 0.0f;
        #pragma unroll
        for (int i = 0; i < NBLK / BT; i++) v += g_partial[tid + BT * i];
        sdist[tid] = v;
        __syncthreads();
        #pragma unroll
        for (int st = BT / 2; st > 0; st >>= 1) {
            if (tid < st) sdist[tid] += sdist[tid + st];
            __syncthreads();
        }
        if (tid == 0) out[0] = sdist[0] * (1.0f / (float)TOTAL);
    }
}

extern "C" void kernel_launch(void* const* d_in, const int* in_sizes, int n_in,
                              void* d_out, int out_size) {
    const float* x = (const float*)d_in[0];
    const float* y = (const float*)d_in[1];
    float* out = (float*)d_out;

    hist_kernel<<<256, 256>>>(x, y);
    prefix_kernel<<<ROWS, 512>>>();
    scatter_kernel<<<256, 256>>>(x, y);
    chamfer_kernel<<<NBLK, BT>>>(out);
}